// round 15
// baseline (speedup 1.0000x reference)
#include <cuda_runtime.h>
#include <math.h>

#define NCOLS 16384
#define NT    256
#define V4    (NCOLS / 4 / NT)      // 16 float4 per thread
#define NW    (NT / 32)             // 8 warps
#define WCAP  384                   // per-warp candidate slots (8-sigma margin)
#define C2CAP 512
#define KSEL  256
#define FTZ   0.70f                 // pre-threshold in z units
#define XTHR  1.40f                 // = 2*FTZ, compare on raw logits

// generic warp-collective tau solve over a strided buffer (fallback path)
__device__ __forceinline__ void solve_buf(const float* __restrict__ cb, int n,
                                          float scale, float cutoff, float zmax,
                                          int lane, float& tau_o, float& th_o,
                                          float& inv_o, int& useGe_o, int& sel_o)
{
    float tau = cutoff, gfin = 0.f;
    for (int it = 0; it < 24; ++it) {
        float g = 0.f, gp = 0.f;
        for (int i = lane; i < n; i += 32) {
            float d = scale * cb[i] - tau;
            if (d > 0.f) { g = fmaf(d, d, g); gp += d; }
        }
        #pragma unroll
        for (int o = 16; o; o >>= 1) {
            g  += __shfl_xor_sync(0xffffffffu, g,  o);
            gp += __shfl_xor_sync(0xffffffffu, gp, o);
        }
        gfin = g;
        g -= 1.0f;
        if (gp <= 0.f) break;
        float step = g / (2.0f * gp);
        tau += step;
        if (step < 1e-7f) break;
    }
    int S = 0;
    for (int i = lane; i < n; i += 32) S += (scale * cb[i] > tau) ? 1 : 0;
    #pragma unroll
    for (int o = 16; o; o >>= 1) S += __shfl_xor_sync(0xffffffffu, S, o);

    float th = tau; int useGe = 0; float ssum = gfin;
    if (S > KSEL) {
        useGe = 1;
        float lo = tau, hi = zmax;
        for (int it = 0; it < 48; ++it) {
            float mid = 0.5f * (lo + hi);
            int c = 0;
            for (int i = lane; i < n; i += 32) c += (scale * cb[i] >= mid) ? 1 : 0;
            #pragma unroll
            for (int o = 16; o; o >>= 1) c += __shfl_xor_sync(0xffffffffu, c, o);
            if (c >= KSEL) lo = mid; else hi = mid;
        }
        th = lo;
        ssum = 0.f;
        for (int i = lane; i < n; i += 32) {
            float z = scale * cb[i], d = z - tau;
            if (z >= th && d > 0.f) ssum = fmaf(d, d, ssum);
        }
        #pragma unroll
        for (int o = 16; o; o >>= 1) ssum += __shfl_xor_sync(0xffffffffu, ssum, o);
    }
    float inv = 1.0f / (ssum + 1e-8f);
    int sel = 0;
    for (int i = lane; i < n; i += 32) {
        float z = scale * cb[i], d = z - tau;
        bool keep = useGe ? (z >= th && d > 0.f) : (d > 0.f);
        sel += ((keep ? d * d * inv : 0.f) > 1e-6f);
    }
    #pragma unroll
    for (int o = 16; o; o >>= 1) sel += __shfl_xor_sync(0xffffffffu, sel, o);
    tau_o = tau; th_o = th; inv_o = inv; useGe_o = useGe; sel_o = sel;
}

__global__ __launch_bounds__(NT, 8)
void entmax_topk_kernel(const float* __restrict__ logits,
                        float* __restrict__ out_w,
                        float* __restrict__ out_cnt)
{
    __shared__ float          swv[NW * WCAP];     // per-warp candidate values (z)
    __shared__ unsigned short swi[NW * WCAP];     // per-warp candidate columns
    __shared__ float          cand2[C2CAP];       // true-cutoff filtered (warp0)
    __shared__ float s_f[NW];
    __shared__ int   s_i[NW];
    __shared__ float s_tau, s_th, s_inv;
    __shared__ int   s_useGe, s_big;

    const int tid  = threadIdx.x;
    const int lane = tid & 31;
    const int wid  = tid >> 5;
    const int row  = blockIdx.x;
    const unsigned lmlt = (1u << lane) - 1u;

    const float4* src = reinterpret_cast<const float4*>(logits) + (size_t)row * (NCOLS / 4);
    float4*       dst = reinterpret_cast<float4*>(out_w)        + (size_t)row * (NCOLS / 4);
    float*          wv  = swv + wid * WCAP;
    unsigned short* wix = swi + wid * WCAP;

    // ---- Pass A: single DRAM sweep = max + ballot-compaction of x > XTHR ----
    float xmax = -INFINITY;
    int   wcnt = 0;
    #pragma unroll 4
    for (int j = 0; j < V4; ++j) {
        float4 t = __ldcs(&src[tid + j * NT]);
        xmax = fmaxf(xmax, fmaxf(fmaxf(t.x, t.y), fmaxf(t.z, t.w)));
        const int col = 4 * (tid + j * NT);
        {
            bool p = t.x > XTHR; unsigned m = __ballot_sync(0xffffffffu, p);
            if (p) { int o = wcnt + __popc(m & lmlt);
                     if (o < WCAP) { wv[o] = 0.5f * t.x; wix[o] = (unsigned short)col; } }
            wcnt += __popc(m);
        }
        {
            bool p = t.y > XTHR; unsigned m = __ballot_sync(0xffffffffu, p);
            if (p) { int o = wcnt + __popc(m & lmlt);
                     if (o < WCAP) { wv[o] = 0.5f * t.y; wix[o] = (unsigned short)(col + 1); } }
            wcnt += __popc(m);
        }
        {
            bool p = t.z > XTHR; unsigned m = __ballot_sync(0xffffffffu, p);
            if (p) { int o = wcnt + __popc(m & lmlt);
                     if (o < WCAP) { wv[o] = 0.5f * t.z; wix[o] = (unsigned short)(col + 2); } }
            wcnt += __popc(m);
        }
        {
            bool p = t.w > XTHR; unsigned m = __ballot_sync(0xffffffffu, p);
            if (p) { int o = wcnt + __popc(m & lmlt);
                     if (o < WCAP) { wv[o] = 0.5f * t.w; wix[o] = (unsigned short)(col + 3); } }
            wcnt += __popc(m);
        }
    }
    #pragma unroll
    for (int o = 16; o; o >>= 1) xmax = fmaxf(xmax, __shfl_xor_sync(0xffffffffu, xmax, o));
    if (lane == 0) { s_f[wid] = xmax; s_i[wid] = wcnt; }

    // ---- zero-fill output (write-only stream; no dependency on the solve) ----
    const float4 zer = make_float4(0.f, 0.f, 0.f, 0.f);
    #pragma unroll 4
    for (int j = 0; j < V4; ++j) __stcs(&dst[tid + j * NT], zer);

    __syncthreads();                               // barrier 1

    float zmax;
    {
        float m = -INFINITY;
        #pragma unroll
        for (int w = 0; w < NW; ++w) m = fmaxf(m, s_f[w]);
        zmax = 0.5f * m;
    }
    const float cutoff = zmax - 1.0f;              // rigorous lower bound on tau
    bool big = (cutoff < FTZ);                     // superset invalid (rare)
    #pragma unroll
    for (int w = 0; w < NW; ++w) big |= (s_i[w] > WCAP);

    // ---- warp 0: pre-filter -> reg-cached solve (or global-row fallback) ----
    if (wid == 0) {
        float tau, th, inv; int useGe, sel;
        bool wbig = big;
        int c2 = 0;
        if (!wbig) {
            // ballot-compact true candidates (z > cutoff) from warp lists into cand2
            for (int w = 0; w < NW; ++w) {
                const int c = s_i[w];
                const int iters = (c + 31) >> 5;
                for (int it = 0; it < iters; ++it) {
                    int i = it * 32 + lane;
                    bool valid = (i < c);
                    float z = valid ? swv[w * WCAP + i] : -1e30f;
                    bool p = valid && (z > cutoff);
                    unsigned m = __ballot_sync(0xffffffffu, p);
                    if (p) { int o = c2 + __popc(m & lmlt); if (o < C2CAP) cand2[o] = z; }
                    c2 += __popc(m);
                }
            }
            if (c2 > C2CAP) wbig = true;
        }
        if (!wbig) {
            // reg-cached Newton over <=512 true candidates
            float rv[C2CAP / 32];
            #pragma unroll
            for (int r = 0; r < C2CAP / 32; ++r) {
                int idx = r * 32 + lane;
                rv[r] = (idx < c2) ? cand2[idx] : -1e30f;
            }
            tau = cutoff;
            float gfin = 0.f;
            for (int it = 0; it < 24; ++it) {
                float g = 0.f, gp = 0.f;
                #pragma unroll
                for (int r = 0; r < C2CAP / 32; ++r) {
                    float d = rv[r] - tau;
                    if (d > 0.f) { g = fmaf(d, d, g); gp += d; }
                }
                #pragma unroll
                for (int o = 16; o; o >>= 1) {
                    g  += __shfl_xor_sync(0xffffffffu, g,  o);
                    gp += __shfl_xor_sync(0xffffffffu, gp, o);
                }
                gfin = g;
                g -= 1.0f;
                if (gp <= 0.f) break;
                float step = g / (2.0f * gp);
                tau += step;
                if (step < 1e-7f) break;
            }
            int S = 0;
            #pragma unroll
            for (int r = 0; r < C2CAP / 32; ++r) S += (rv[r] > tau) ? 1 : 0;
            #pragma unroll
            for (int o = 16; o; o >>= 1) S += __shfl_xor_sync(0xffffffffu, S, o);
            th = tau; useGe = 0;
            float ssum = gfin;
            if (S > KSEL) {                        // rare: bisect K-th largest z
                useGe = 1;
                float lo = tau, hi = zmax;
                for (int it = 0; it < 48; ++it) {
                    float mid = 0.5f * (lo + hi);
                    int c = 0;
                    #pragma unroll
                    for (int r = 0; r < C2CAP / 32; ++r) c += (rv[r] >= mid) ? 1 : 0;
                    #pragma unroll
                    for (int o = 16; o; o >>= 1) c += __shfl_xor_sync(0xffffffffu, c, o);
                    if (c >= KSEL) lo = mid; else hi = mid;
                }
                th = lo;
                ssum = 0.f;
                #pragma unroll
                for (int r = 0; r < C2CAP / 32; ++r) {
                    float z = rv[r], d = z - tau;
                    if (z >= th && d > 0.f) ssum = fmaf(d, d, ssum);
                }
                #pragma unroll
                for (int o = 16; o; o >>= 1) ssum += __shfl_xor_sync(0xffffffffu, ssum, o);
            }
            inv = 1.0f / (ssum + 1e-8f);
            sel = 0;
            #pragma unroll
            for (int r = 0; r < C2CAP / 32; ++r) {
                float z = rv[r], d = z - tau;
                bool keep = useGe ? (z >= th && d > 0.f) : (d > 0.f);
                sel += ((keep ? d * d * inv : 0.f) > 1e-6f);
            }
            #pragma unroll
            for (int o = 16; o; o >>= 1) sel += __shfl_xor_sync(0xffffffffu, sel, o);
        } else {
            // exact fallback: solve over the full global row
            solve_buf(logits + (size_t)row * NCOLS, NCOLS, 0.5f, cutoff, zmax, lane,
                      tau, th, inv, useGe, sel);
        }
        if (lane == 0) {
            s_tau = tau; s_th = th; s_useGe = useGe; s_inv = inv;
            s_big = wbig ? 1 : 0;
            out_cnt[row] = (float)sel;
        }
    }
    __syncthreads();                               // barrier 2 (last)

    const float tau = s_tau, th = s_th, inv = s_inv;
    const bool  useGe = (s_useGe != 0);

    if (!s_big) {
        // ---- scatter the few nonzero weights over the zero-filled row ----
        float* orow = out_w + (size_t)row * NCOLS;
        #pragma unroll
        for (int w = 0; w < NW; ++w) {
            const int c = s_i[w];                  // <= WCAP on this path
            for (int i = tid; i < c; i += NT) {
                float z = swv[w * WCAP + i], d = z - tau;
                bool keep = useGe ? (z >= th && d > 0.f) : (d > 0.f);
                if (keep) orow[swi[w * WCAP + i]] = d * d * inv;
            }
        }
    } else {
        // exact full output stream (zero-fill gets overwritten)
        #pragma unroll 4
        for (int j = 0; j < V4; ++j) {
            float4 t = src[tid + j * NT];
            float4 w;
            { float z = 0.5f*t.x, d = z-tau; bool k = useGe ? (z>=th && d>0.f):(d>0.f); w.x = k ? d*d*inv : 0.f; }
            { float z = 0.5f*t.y, d = z-tau; bool k = useGe ? (z>=th && d>0.f):(d>0.f); w.y = k ? d*d*inv : 0.f; }
            { float z = 0.5f*t.z, d = z-tau; bool k = useGe ? (z>=th && d>0.f):(d>0.f); w.z = k ? d*d*inv : 0.f; }
            { float z = 0.5f*t.w, d = z-tau; bool k = useGe ? (z>=th && d>0.f):(d>0.f); w.w = k ? d*d*inv : 0.f; }
            __stcs(&dst[tid + j * NT], w);
        }
    }
}

extern "C" void kernel_launch(void* const* d_in, const int* in_sizes, int n_in,
                              void* d_out, int out_size)
{
    const float* logits = (const float*)d_in[0];
    float* out = (float*)d_out;
    const int B = in_sizes[0] / NCOLS;
    entmax_topk_kernel<<<B, NT>>>(logits, out, out + (size_t)B * NCOLS);
}

// round 16
// speedup vs baseline: 2.3519x; 2.3519x over previous
#include <cuda_runtime.h>
#include <math.h>

#define NCOLS 16384
#define NT    512
#define V4    (NCOLS / 4 / NT)     // 8 float4 per thread
#define NW    (NT / 32)            // 16 warps
#define KSEL  256
#define CAP   1408                 // superset capacity (mean ~1094, ~10 sigma)
#define C2CAP 512
#define FTZ   0.75f                // fixed pre-threshold (z units)

// generic warp-collective tau solve (z-units buffer), with num_selected
__device__ __forceinline__ void solve_buf(const float* __restrict__ cb, int n,
                                          float cutoff, float zmax, int lane,
                                          float& tau_o, float& th_o, float& inv_o,
                                          int& useGe_o, int& sel_o)
{
    float tau = cutoff, gfin = 0.f;
    for (int it = 0; it < 24; ++it) {
        float g = 0.f, gp = 0.f;
        for (int i = lane; i < n; i += 32) {
            float d = cb[i] - tau;
            if (d > 0.f) { g = fmaf(d, d, g); gp += d; }
        }
        #pragma unroll
        for (int o = 16; o; o >>= 1) {
            g  += __shfl_xor_sync(0xffffffffu, g,  o);
            gp += __shfl_xor_sync(0xffffffffu, gp, o);
        }
        gfin = g;
        g -= 1.0f;
        if (gp <= 0.f) break;
        float step = g / (2.0f * gp);
        tau += step;
        if (step < 1e-7f) break;
    }
    int S = 0;
    for (int i = lane; i < n; i += 32) S += (cb[i] > tau) ? 1 : 0;
    #pragma unroll
    for (int o = 16; o; o >>= 1) S += __shfl_xor_sync(0xffffffffu, S, o);

    float th = tau; int useGe = 0; float ssum = gfin;
    if (S > KSEL) {                        // rare: bisect K-th largest z
        useGe = 1;
        float lo = tau, hi = zmax;
        for (int it = 0; it < 48; ++it) {
            float mid = 0.5f * (lo + hi);
            int c = 0;
            for (int i = lane; i < n; i += 32) c += (cb[i] >= mid) ? 1 : 0;
            #pragma unroll
            for (int o = 16; o; o >>= 1) c += __shfl_xor_sync(0xffffffffu, c, o);
            if (c >= KSEL) lo = mid; else hi = mid;
        }
        th = lo;
        ssum = 0.f;
        for (int i = lane; i < n; i += 32) {
            float z = cb[i], d = z - tau;
            if (z >= th && d > 0.f) ssum = fmaf(d, d, ssum);
        }
        #pragma unroll
        for (int o = 16; o; o >>= 1) ssum += __shfl_xor_sync(0xffffffffu, ssum, o);
    }
    float inv = 1.0f / (ssum + 1e-8f);
    int sel = 0;
    for (int i = lane; i < n; i += 32) {
        float z = cb[i], d = z - tau;
        bool keep = useGe ? (z >= th && d > 0.f) : (d > 0.f);
        sel += ((keep ? d * d * inv : 0.f) > 1e-6f);
    }
    #pragma unroll
    for (int o = 16; o; o >>= 1) sel += __shfl_xor_sync(0xffffffffu, sel, o);
    tau_o = tau; th_o = th; inv_o = inv; useGe_o = useGe; sel_o = sel;
}

__global__ __launch_bounds__(NT, 3)
void entmax_topk_kernel(const float* __restrict__ logits,
                        float* __restrict__ out_w,
                        float* __restrict__ out_cnt)
{
    extern __shared__ float smbuf[];
    float*          zs    = smbuf;                                  // NCOLS floats
    float*          cand  = smbuf + NCOLS;                          // CAP floats
    unsigned short* cidx  = (unsigned short*)(cand + CAP);          // CAP ushorts
    float*          cand2 = (float*)(cidx + CAP);                   // C2CAP floats

    __shared__ float s_f[NW];
    __shared__ int   s_i[NW];
    __shared__ float s_tau, s_th, s_inv;
    __shared__ int   s_useGe;

    const int tid  = threadIdx.x;
    const int lane = tid & 31;
    const int wid  = tid >> 5;
    const int row  = blockIdx.x;
    const unsigned lmlt = (1u << lane) - 1u;

    const float4* src = reinterpret_cast<const float4*>(logits) + (size_t)row * (NCOLS / 4);
    float4*       dst = reinterpret_cast<float4*>(out_w)        + (size_t)row * (NCOLS / 4);
    float4*       zs4 = reinterpret_cast<float4*>(zs);

    // ---- Pass A: ONE DRAM sweep = smem row + max + count(z > FTZ). Stream-legal ops only. ----
    float lmax = -INFINITY;
    int   lc = 0;
    #pragma unroll
    for (int j = 0; j < V4; ++j) {
        const int i = tid + j * NT;
        float4 t = __ldcs(&src[i]);
        t.x *= 0.5f; t.y *= 0.5f; t.z *= 0.5f; t.w *= 0.5f;
        zs4[i] = t;
        lmax = fmaxf(lmax, fmaxf(fmaxf(t.x, t.y), fmaxf(t.z, t.w)));
        lc += (t.x > FTZ) + (t.y > FTZ) + (t.z > FTZ) + (t.w > FTZ);
    }
    // zero-fill output now: write-only stream, drains during the solve phases
    const float4 zer = make_float4(0.f, 0.f, 0.f, 0.f);
    #pragma unroll
    for (int j = 0; j < V4; ++j) __stcs(&dst[tid + j * NT], zer);

    #pragma unroll
    for (int o = 16; o; o >>= 1) lmax = fmaxf(lmax, __shfl_xor_sync(0xffffffffu, lmax, o));
    int inc = lc;
    #pragma unroll
    for (int o = 1; o < 32; o <<= 1) {
        int t = __shfl_up_sync(0xffffffffu, inc, o);
        if (lane >= o) inc += t;
    }
    if (lane == 0)  s_f[wid] = lmax;
    if (lane == 31) s_i[wid] = inc;
    __syncthreads();                                 // barrier 1

    float zmax; int cn, wbase;
    {
        float m = (lane < NW) ? s_f[lane] : -INFINITY;
        #pragma unroll
        for (int o = 8; o; o >>= 1) m = fmaxf(m, __shfl_xor_sync(0xffffffffu, m, o));
        zmax = __shfl_sync(0xffffffffu, m, 0);
        int a = (lane < NW) ? s_i[lane] : 0;
        int sc = a;
        #pragma unroll
        for (int o = 1; o < NW; o <<= 1) {
            int u = __shfl_up_sync(0xffffffffu, sc, o);
            if (lane >= o) sc += u;
        }
        cn    = __shfl_sync(0xffffffffu, sc, NW - 1);
        wbase = __shfl_sync(0xffffffffu, sc - a, wid);
    }
    const float cutoff = zmax - 1.0f;                // rigorous lower bound on tau
    float thr = FTZ;

    if (cutoff < FTZ) {                              // block-uniform exact recount (~2% rows)
        thr = cutoff;
        int l2 = 0;
        #pragma unroll
        for (int j = 0; j < V4; ++j) {
            float4 t = zs4[tid + j * NT];
            l2 += (t.x > cutoff) + (t.y > cutoff) + (t.z > cutoff) + (t.w > cutoff);
        }
        int inc2 = l2;
        #pragma unroll
        for (int o = 1; o < 32; o <<= 1) {
            int t = __shfl_up_sync(0xffffffffu, inc2, o);
            if (lane >= o) inc2 += t;
        }
        __syncthreads();                             // protect s_i reuse
        if (lane == 31) s_i[wid] = inc2;
        __syncthreads();
        int a = (lane < NW) ? s_i[lane] : 0;
        int sc = a;
        #pragma unroll
        for (int o = 1; o < NW; o <<= 1) {
            int u = __shfl_up_sync(0xffffffffu, sc, o);
            if (lane >= o) sc += u;
        }
        cn    = __shfl_sync(0xffffffffu, sc, NW - 1);
        wbase = __shfl_sync(0xffffffffu, sc - a, wid);
        inc = inc2; lc = l2;
    }

    const bool big = (cn > CAP);                     // astronomically rare
    if (!big && lc > 0) {
        // compact superset (z > thr) with column indices, from own smem elements
        int o = wbase + (inc - lc);
        #pragma unroll
        for (int j = 0; j < V4; ++j) {
            const int i = tid + j * NT;
            float4 t = zs4[i];
            const int base = 4 * i;
            if (t.x > thr) { cand[o] = t.x; cidx[o] = (unsigned short)(base);     ++o; }
            if (t.y > thr) { cand[o] = t.y; cidx[o] = (unsigned short)(base + 1); ++o; }
            if (t.z > thr) { cand[o] = t.z; cidx[o] = (unsigned short)(base + 2); ++o; }
            if (t.w > thr) { cand[o] = t.w; cidx[o] = (unsigned short)(base + 3); ++o; }
        }
    }
    __syncthreads();                                 // barrier 2

    // ---- warp 0: prefilter (warp0-only ballots = legal) + reg-cached solve ----
    if (wid == 0) {
        float tau, th, inv; int useGe, sel;
        if (!big) {
            int c2 = 0;
            const int iters = (cn + 31) >> 5;
            for (int it = 0; it < iters; ++it) {
                int i = it * 32 + lane;
                bool v = (i < cn);
                float z = v ? cand[i] : -1e30f;
                bool p = v && (z > cutoff);
                unsigned m = __ballot_sync(0xffffffffu, p);
                if (p) { int o = c2 + __popc(m & lmlt); if (o < C2CAP) cand2[o] = z; }
                c2 += __popc(m);
            }
            if (c2 <= C2CAP) {
                // reg-cached Newton over exact candidate set (typ ~175)
                float rv[C2CAP / 32];
                #pragma unroll
                for (int r = 0; r < C2CAP / 32; ++r) {
                    int idx = r * 32 + lane;
                    rv[r] = (idx < c2) ? cand2[idx] : -1e30f;
                }
                tau = cutoff;
                float gfin = 0.f;
                for (int it = 0; it < 24; ++it) {
                    float g = 0.f, gp = 0.f;
                    #pragma unroll
                    for (int r = 0; r < C2CAP / 32; ++r) {
                        float d = rv[r] - tau;
                        if (d > 0.f) { g = fmaf(d, d, g); gp += d; }
                    }
                    #pragma unroll
                    for (int o = 16; o; o >>= 1) {
                        g  += __shfl_xor_sync(0xffffffffu, g,  o);
                        gp += __shfl_xor_sync(0xffffffffu, gp, o);
                    }
                    gfin = g;
                    g -= 1.0f;
                    if (gp <= 0.f) break;
                    float step = g / (2.0f * gp);
                    tau += step;
                    if (step < 1e-7f) break;
                }
                int S = 0;
                #pragma unroll
                for (int r = 0; r < C2CAP / 32; ++r) S += (rv[r] > tau) ? 1 : 0;
                #pragma unroll
                for (int o = 16; o; o >>= 1) S += __shfl_xor_sync(0xffffffffu, S, o);
                th = tau; useGe = 0;
                float ssum = gfin;
                if (S > KSEL) {                      // rare: bisect K-th largest z
                    useGe = 1;
                    float lo = tau, hi = zmax;
                    for (int it = 0; it < 48; ++it) {
                        float mid = 0.5f * (lo + hi);
                        int c = 0;
                        #pragma unroll
                        for (int r = 0; r < C2CAP / 32; ++r) c += (rv[r] >= mid) ? 1 : 0;
                        #pragma unroll
                        for (int o = 16; o; o >>= 1) c += __shfl_xor_sync(0xffffffffu, c, o);
                        if (c >= KSEL) lo = mid; else hi = mid;
                    }
                    th = lo;
                    ssum = 0.f;
                    #pragma unroll
                    for (int r = 0; r < C2CAP / 32; ++r) {
                        float z = rv[r], d = z - tau;
                        if (z >= th && d > 0.f) ssum = fmaf(d, d, ssum);
                    }
                    #pragma unroll
                    for (int o = 16; o; o >>= 1) ssum += __shfl_xor_sync(0xffffffffu, ssum, o);
                }
                inv = 1.0f / (ssum + 1e-8f);
                sel = 0;
                #pragma unroll
                for (int r = 0; r < C2CAP / 32; ++r) {
                    float z = rv[r], d = z - tau;
                    bool keep = useGe ? (z >= th && d > 0.f) : (d > 0.f);
                    sel += ((keep ? d * d * inv : 0.f) > 1e-6f);
                }
                #pragma unroll
                for (int o = 16; o; o >>= 1) sel += __shfl_xor_sync(0xffffffffu, sel, o);
            } else {
                // exact: solve over the full superset (elements < tau contribute 0)
                solve_buf(cand, cn, cutoff, zmax, lane, tau, th, inv, useGe, sel);
            }
        } else {
            // overflow fallback: solve over the full smem row
            solve_buf(zs, NCOLS, cutoff, zmax, lane, tau, th, inv, useGe, sel);
        }
        if (lane == 0) {
            s_tau = tau; s_th = th; s_useGe = useGe; s_inv = inv;
            out_cnt[row] = (float)sel;
        }
    }
    __syncthreads();                                 // barrier 3 (last)

    const float tau = s_tau, th = s_th, inv = s_inv;
    const bool  useGe = (s_useGe != 0);

    if (!big) {
        // ---- scatter: only superset entries can be nonzero ----
        float* orow = out_w + (size_t)row * NCOLS;
        for (int i = tid; i < cn; i += NT) {
            float z = cand[i], d = z - tau;
            bool keep = useGe ? (z >= th && d > 0.f) : (d > 0.f);
            if (keep) orow[cidx[i]] = d * d * inv;
        }
    } else {
        // exact full output from smem row (overwrites zero-fill)
        #pragma unroll
        for (int j = 0; j < V4; ++j) {
            float4 t = zs4[tid + j * NT];
            float4 w;
            { float z = t.x, d = z - tau; bool k = useGe ? (z >= th && d > 0.f) : (d > 0.f); w.x = k ? d * d * inv : 0.f; }
            { float z = t.y, d = z - tau; bool k = useGe ? (z >= th && d > 0.f) : (d > 0.f); w.y = k ? d * d * inv : 0.f; }
            { float z = t.z, d = z - tau; bool k = useGe ? (z >= th && d > 0.f) : (d > 0.f); w.z = k ? d * d * inv : 0.f; }
            { float z = t.w, d = z - tau; bool k = useGe ? (z >= th && d > 0.f) : (d > 0.f); w.w = k ? d * d * inv : 0.f; }
            __stcs(&dst[tid + j * NT], w);
        }
    }
}

extern "C" void kernel_launch(void* const* d_in, const int* in_sizes, int n_in,
                              void* d_out, int out_size)
{
    const float* logits = (const float*)d_in[0];
    float* out = (float*)d_out;
    const int B = in_sizes[0] / NCOLS;

    // dynamic smem: row + superset values + ushort indices + filtered buffer
    const size_t smem = (size_t)NCOLS * 4 + (size_t)CAP * 4 + (size_t)CAP * 2 + (size_t)C2CAP * 4;
    cudaFuncSetAttribute(entmax_topk_kernel,
                         cudaFuncAttributeMaxDynamicSharedMemorySize, (int)smem);
    entmax_topk_kernel<<<B, NT, smem>>>(logits, out, out + (size_t)B * NCOLS);
}